// round 1
// baseline (speedup 1.0000x reference)
#include <cuda_runtime.h>
#include <cstddef>

#define NT 8192
#define CD 512
#define DKD 64

// ---------------- scratch (device globals; no allocations allowed) ----------
__device__ float g_S[(size_t)NT * NT];          // 256 MB attention scratch (reused)
__device__ float g_Q1[NT * DKD];
__device__ float g_K1[NT * DKD];
__device__ float g_Q2[NT * DKD];
__device__ float g_K2[NT * DKD];
__device__ float g_V1[(size_t)NT * CD];
__device__ float g_V2[(size_t)NT * CD];

// ---------------- generic NN sgemm: C = A[MxK] @ B[KxN] (+Res) --------------
// 128x128 block tile, 8x8 per thread, BK=8, double-buffered smem.
__global__ __launch_bounds__(256, 2)
void gemm_nn_kernel(const float* __restrict__ A, const float* __restrict__ B,
                    const float* __restrict__ Res, float* __restrict__ C,
                    int M, int N, int K)
{
    constexpr int BM = 128, BN = 128, BK = 8, TM = 8, TN = 8;
    __shared__ float As[2][BK][BM];
    __shared__ float Bs[2][BK][BN];

    const int tid = threadIdx.x;
    const int tx = tid & 15;
    const int ty = tid >> 4;
    const int row0 = blockIdx.y * BM;
    const int col0 = blockIdx.x * BN;

    const int a_row = tid >> 1;           // 0..127
    const int a_col = (tid & 1) << 2;     // 0 or 4
    const int b_row = tid >> 5;           // 0..7
    const int b_col = (tid & 31) << 2;    // 0..124

    const float* Aptr = A + (size_t)(row0 + a_row) * K + a_col;
    const float* Bptr = B + (size_t)b_row * N + (col0 + b_col);
    const bool bvalid = (col0 + b_col) < N;

    float acc[TM][TN];
#pragma unroll
    for (int i = 0; i < TM; i++)
#pragma unroll
        for (int j = 0; j < TN; j++) acc[i][j] = 0.f;

    // prologue: tile 0
    float4 a = *(const float4*)Aptr;
    float4 b = bvalid ? *(const float4*)Bptr : make_float4(0.f, 0.f, 0.f, 0.f);
    As[0][a_col + 0][a_row] = a.x;
    As[0][a_col + 1][a_row] = a.y;
    As[0][a_col + 2][a_row] = a.z;
    As[0][a_col + 3][a_row] = a.w;
    *(float4*)&Bs[0][b_row][b_col] = b;
    __syncthreads();

    int buf = 0;
    for (int kt = 0; kt < K; kt += BK) {
        const int ktn = kt + BK;
        float4 an, bn;
        if (ktn < K) {
            an = *(const float4*)(Aptr + ktn);
            bn = bvalid ? *(const float4*)(Bptr + (size_t)ktn * N)
                        : make_float4(0.f, 0.f, 0.f, 0.f);
        }
#pragma unroll
        for (int kk = 0; kk < BK; kk++) {
            float af[TM], bf[TN];
#pragma unroll
            for (int i = 0; i < TM; i++) af[i] = As[buf][kk][ty * TM + i];
#pragma unroll
            for (int j = 0; j < TN; j++) bf[j] = Bs[buf][kk][tx * TN + j];
#pragma unroll
            for (int i = 0; i < TM; i++)
#pragma unroll
                for (int j = 0; j < TN; j++) acc[i][j] += af[i] * bf[j];
        }
        if (ktn < K) {
            buf ^= 1;
            As[buf][a_col + 0][a_row] = an.x;
            As[buf][a_col + 1][a_row] = an.y;
            As[buf][a_col + 2][a_row] = an.z;
            As[buf][a_col + 3][a_row] = an.w;
            *(float4*)&Bs[buf][b_row][b_col] = bn;
            __syncthreads();
        }
    }

    // epilogue
#pragma unroll
    for (int i = 0; i < TM; i++) {
        const int r = row0 + ty * TM + i;
#pragma unroll
        for (int j = 0; j < TN; j += 4) {
            const int c = col0 + tx * TN + j;
            if (c < N) {
                float4 v = make_float4(acc[i][j], acc[i][j + 1],
                                       acc[i][j + 2], acc[i][j + 3]);
                if (Res) {
                    const float4 rv = *(const float4*)(Res + (size_t)r * N + c);
                    v.x += rv.x; v.y += rv.y; v.z += rv.z; v.w += rv.w;
                }
                *(float4*)(C + (size_t)r * N + c) = v;
            }
        }
    }
}

// ---------------- NT sgemm: S[MxN] = Q[Mx64] @ Kmat[Nx64]^T ----------------
__global__ __launch_bounds__(256, 2)
void gemm_nt_kernel(const float* __restrict__ Q, const float* __restrict__ Kmat,
                    float* __restrict__ S)
{
    constexpr int BM = 128, BN = 128, BK = 8, TM = 8, TN = 8, KD = DKD;
    __shared__ float As[2][BK][BM];
    __shared__ float Bs[2][BK][BN];

    const int tid = threadIdx.x;
    const int tx = tid & 15;
    const int ty = tid >> 4;
    const int row0 = blockIdx.y * BM;
    const int col0 = blockIdx.x * BN;

    const int l_row = tid >> 1;           // 0..127
    const int l_col = (tid & 1) << 2;     // 0 or 4

    const float* Qptr = Q + (size_t)(row0 + l_row) * KD + l_col;
    const float* Kptr = Kmat + (size_t)(col0 + l_row) * KD + l_col;

    float acc[TM][TN];
#pragma unroll
    for (int i = 0; i < TM; i++)
#pragma unroll
        for (int j = 0; j < TN; j++) acc[i][j] = 0.f;

    float4 a = *(const float4*)Qptr;
    float4 b = *(const float4*)Kptr;
    As[0][l_col + 0][l_row] = a.x;
    As[0][l_col + 1][l_row] = a.y;
    As[0][l_col + 2][l_row] = a.z;
    As[0][l_col + 3][l_row] = a.w;
    Bs[0][l_col + 0][l_row] = b.x;
    Bs[0][l_col + 1][l_row] = b.y;
    Bs[0][l_col + 2][l_row] = b.z;
    Bs[0][l_col + 3][l_row] = b.w;
    __syncthreads();

    int buf = 0;
#pragma unroll
    for (int kt = 0; kt < KD; kt += BK) {
        const int ktn = kt + BK;
        float4 an, bn;
        if (ktn < KD) {
            an = *(const float4*)(Qptr + ktn);
            bn = *(const float4*)(Kptr + ktn);
        }
#pragma unroll
        for (int kk = 0; kk < BK; kk++) {
            float af[TM], bf[TN];
#pragma unroll
            for (int i = 0; i < TM; i++) af[i] = As[buf][kk][ty * TM + i];
#pragma unroll
            for (int j = 0; j < TN; j++) bf[j] = Bs[buf][kk][tx * TN + j];
#pragma unroll
            for (int i = 0; i < TM; i++)
#pragma unroll
                for (int j = 0; j < TN; j++) acc[i][j] += af[i] * bf[j];
        }
        if (ktn < KD) {
            buf ^= 1;
            As[buf][l_col + 0][l_row] = an.x;
            As[buf][l_col + 1][l_row] = an.y;
            As[buf][l_col + 2][l_row] = an.z;
            As[buf][l_col + 3][l_row] = an.w;
            Bs[buf][l_col + 0][l_row] = bn.x;
            Bs[buf][l_col + 1][l_row] = bn.y;
            Bs[buf][l_col + 2][l_row] = bn.z;
            Bs[buf][l_col + 3][l_row] = bn.w;
            __syncthreads();
        }
    }

#pragma unroll
    for (int i = 0; i < TM; i++) {
        const int r = row0 + ty * TM + i;
#pragma unroll
        for (int j = 0; j < TN; j += 4) {
            const int c = col0 + tx * TN + j;
            float4 v = make_float4(acc[i][j], acc[i][j + 1],
                                   acc[i][j + 2], acc[i][j + 3]);
            *(float4*)(S + (size_t)r * NT + c) = v;
        }
    }
}

// ---------------- row softmax over 8192-wide rows, in place ----------------
__device__ __forceinline__ float warp_max(float v) {
#pragma unroll
    for (int o = 16; o > 0; o >>= 1) v = fmaxf(v, __shfl_xor_sync(0xffffffffu, v, o));
    return v;
}
__device__ __forceinline__ float warp_sum(float v) {
#pragma unroll
    for (int o = 16; o > 0; o >>= 1) v += __shfl_xor_sync(0xffffffffu, v, o);
    return v;
}

__global__ __launch_bounds__(256)
void softmax_kernel(float* __restrict__ S)
{
    __shared__ float row[NT];     // 32 KB
    __shared__ float red[8];
    const int tid = threadIdx.x;
    float* Sr = S + (size_t)blockIdx.x * NT;

    // pass 1: load + max
    float lmax = -3.4e38f;
    for (int i = tid; i < NT / 4; i += 256) {
        const float4 v = ((const float4*)Sr)[i];
        ((float4*)row)[i] = v;
        lmax = fmaxf(lmax, fmaxf(fmaxf(v.x, v.y), fmaxf(v.z, v.w)));
    }
    lmax = warp_max(lmax);
    if ((tid & 31) == 0) red[tid >> 5] = lmax;
    __syncthreads();
    float rmax = red[0];
#pragma unroll
    for (int w = 1; w < 8; w++) rmax = fmaxf(rmax, red[w]);
    __syncthreads();

    // pass 2: exp + sum
    float lsum = 0.f;
    for (int i = tid; i < NT / 4; i += 256) {
        float4 v = ((const float4*)row)[i];
        v.x = __expf(v.x - rmax);
        v.y = __expf(v.y - rmax);
        v.z = __expf(v.z - rmax);
        v.w = __expf(v.w - rmax);
        lsum += v.x + v.y + v.z + v.w;
        ((float4*)row)[i] = v;
    }
    lsum = warp_sum(lsum);
    if ((tid & 31) == 0) red[tid >> 5] = lsum;
    __syncthreads();
    float rsum = 0.f;
#pragma unroll
    for (int w = 0; w < 8; w++) rsum += red[w];
    const float inv = 1.f / rsum;

    // pass 3: normalize + store
    for (int i = tid; i < NT / 4; i += 256) {
        float4 v = ((const float4*)row)[i];
        v.x *= inv; v.y *= inv; v.z *= inv; v.w *= inv;
        ((float4*)Sr)[i] = v;
    }
}

// ---------------- launch -----------------------------------------------------
extern "C" void kernel_launch(void* const* d_in, const int* in_sizes, int n_in,
                              void* d_out, int out_size)
{
    const float* im1 = (const float*)d_in[0];
    const float* im2 = (const float*)d_in[1];
    const float* Wq  = (const float*)d_in[2];
    const float* Wk  = (const float*)d_in[3];
    const float* Wv  = (const float*)d_in[4];

    float* out1 = (float*)d_out;
    float* out2 = out1 + (size_t)NT * CD;

    float *pS, *pQ1, *pK1, *pQ2, *pK2, *pV1, *pV2;
    cudaGetSymbolAddress((void**)&pS,  g_S);
    cudaGetSymbolAddress((void**)&pQ1, g_Q1);
    cudaGetSymbolAddress((void**)&pK1, g_K1);
    cudaGetSymbolAddress((void**)&pQ2, g_Q2);
    cudaGetSymbolAddress((void**)&pK2, g_K2);
    cudaGetSymbolAddress((void**)&pV1, g_V1);
    cudaGetSymbolAddress((void**)&pV2, g_V2);

    const dim3 blk(256);

    // projections
    const dim3 gqk(1, NT / 128);
    gemm_nn_kernel<<<gqk, blk>>>(im1, Wq, nullptr, pQ1, NT, DKD, CD);
    gemm_nn_kernel<<<gqk, blk>>>(im1, Wk, nullptr, pK1, NT, DKD, CD);
    gemm_nn_kernel<<<gqk, blk>>>(im2, Wq, nullptr, pQ2, NT, DKD, CD);
    gemm_nn_kernel<<<gqk, blk>>>(im2, Wk, nullptr, pK2, NT, DKD, CD);
    const dim3 gv(CD / 128, NT / 128);
    gemm_nn_kernel<<<gv, blk>>>(im1, Wv, nullptr, pV1, NT, CD, CD);
    gemm_nn_kernel<<<gv, blk>>>(im2, Wv, nullptr, pV2, NT, CD, CD);

    const dim3 gs(NT / 128, NT / 128);

    // stream 1: im1_out = softmax(Q2 @ K1^T) @ V1 + im1
    gemm_nt_kernel<<<gs, blk>>>(pQ2, pK1, pS);
    softmax_kernel<<<NT, 256>>>(pS);
    gemm_nn_kernel<<<gv, blk>>>(pS, pV1, im1, out1, NT, CD, NT);

    // stream 2: im2_out = softmax(Q1 @ K2^T) @ V2 + im2
    gemm_nt_kernel<<<gs, blk>>>(pQ1, pK2, pS);
    softmax_kernel<<<NT, 256>>>(pS);
    gemm_nn_kernel<<<gv, blk>>>(pS, pV2, im2, out2, NT, CD, NT);
}

// round 2
// speedup vs baseline: 3.6220x; 3.6220x over previous
#include <cuda_runtime.h>
#include <cstdint>
#include <cstddef>

#define NTOK 8192
#define CDIM 512

// ---------------- scratch (device globals; no allocations allowed) ----------
__device__ float g_S[(size_t)NTOK * NTOK];          // 256 MB attention scratch
__device__ float g_QK1[(size_t)NTOK * 128];         // [Q1 | K1]
__device__ float g_QK2[(size_t)NTOK * 128];         // [Q2 | K2]
__device__ float g_V1[(size_t)NTOK * CDIM];
__device__ float g_V2[(size_t)NTOK * CDIM];
__device__ float g_Wqk[(size_t)CDIM * 128];         // [Wq | Wk] packed

// ---------------- helpers ----------------------------------------------------
__device__ __forceinline__ uint32_t f2tf32(float x) {
    uint32_t r;
    asm("cvt.rna.tf32.f32 %0, %1;" : "=r"(r) : "f"(x));
    return r;
}
__device__ __forceinline__ float tf32_round(float x) { return __uint_as_float(f2tf32(x)); }

__device__ __forceinline__ void mma8(float* c, const uint32_t* a, const uint32_t* b) {
    asm volatile(
        "mma.sync.aligned.m16n8k8.row.col.f32.tf32.tf32.f32 "
        "{%0,%1,%2,%3}, {%4,%5,%6,%7}, {%8,%9}, {%0,%1,%2,%3};"
        : "+f"(c[0]), "+f"(c[1]), "+f"(c[2]), "+f"(c[3])
        : "r"(a[0]), "r"(a[1]), "r"(a[2]), "r"(a[3]), "r"(b[0]), "r"(b[1]));
}

__global__ void pack_wqk(const float* __restrict__ Wq, const float* __restrict__ Wk,
                         float* __restrict__ Wqk) {
    const int i = blockIdx.x * 256 + threadIdx.x;   // 512*128
    const int r = i >> 7, c = i & 127;
    Wqk[i] = (c < 64) ? Wq[r * 64 + c] : Wk[r * 64 + (c - 64)];
}

// ---------------- TF32 tensor-core GEMM --------------------------------------
// C[128*gy + :, 128*gx + :] = A @ opB  (+ Res), fp32 acc.
// TRB=true : B is row-major [K x N]  -> transposed into smem (NN math)
// TRB=false: B is row-major [N x K]  -> direct copy            (NT math)
// THREE: 3xTF32 error-compensated (near-fp32 accuracy)
// RND:   round outputs to tf32 (rna) so a later mma sees exact operands
// !THREE also rounds staged operands to tf32-rna (kills truncation bias)
template<bool THREE, bool RND, bool TRB>
__global__ __launch_bounds__(256, THREE ? 1 : 2)
void gemm_tf32(const float* __restrict__ A, int lda,
               const float* __restrict__ B, int ldb,
               const float* __restrict__ Res,
               float* __restrict__ C, int ldc, int K)
{
    constexpr int BK = 16, STR = BK + 8;            // pad 8 -> conflict-free frags
    __shared__ float As[2][128][STR];
    __shared__ float Bs[2][128][STR];

    const int tid  = threadIdx.x;
    const int lane = tid & 31;
    const int wid  = tid >> 5;
    const int wm0  = (wid & 1) << 6;                // 0,64
    const int wn0  = (wid >> 1) << 5;               // 0,32,64,96
    const int lr   = lane >> 2;                     // 0..7
    const int lc2  = (lane & 3) << 1;               // 0,2,4,6

    const size_t row0 = (size_t)blockIdx.y * 128;
    const size_t col0 = (size_t)blockIdx.x * 128;

    // A loader: 2x float4 per thread (rows ar, ar+64)
    const int ar = tid >> 2;                        // 0..63
    const int ac = (tid & 3) << 2;                  // 0,4,8,12
    const float* Ap0 = A + (row0 + ar) * (size_t)lda + ac;
    const float* Ap1 = Ap0 + (size_t)64 * lda;

    // B loader
    const float *Bp0, *Bp1;
    int bk_ = 0, bg4 = 0;
    if (TRB) {
        bk_ = tid & 15;                             // k row
        bg4 = (tid >> 4) << 2;                      // n group 0,4,...,60
        Bp0 = B + (size_t)bk_ * ldb + col0 + bg4;
        Bp1 = Bp0 + 64;
    } else {
        Bp0 = B + (col0 + ar) * (size_t)ldb + ac;
        Bp1 = Bp0 + (size_t)64 * ldb;
    }

    float4 a0 = *(const float4*)Ap0;
    float4 a1 = *(const float4*)Ap1;
    float4 b0 = *(const float4*)Bp0;
    float4 b1 = *(const float4*)Bp1;

    float acc[4][4][4];
#pragma unroll
    for (int i = 0; i < 4; i++)
#pragma unroll
        for (int j = 0; j < 4; j++)
#pragma unroll
            for (int k = 0; k < 4; k++) acc[i][j][k] = 0.f;

    auto q = [](float x) -> float {
        return THREE ? x : __uint_as_float(0u), THREE ? x : tf32_round(x);
    };

    auto store_tiles = [&](int bf, float4 sa0, float4 sa1, float4 sb0, float4 sb1) {
        if (!THREE) {
            sa0.x = tf32_round(sa0.x); sa0.y = tf32_round(sa0.y);
            sa0.z = tf32_round(sa0.z); sa0.w = tf32_round(sa0.w);
            sa1.x = tf32_round(sa1.x); sa1.y = tf32_round(sa1.y);
            sa1.z = tf32_round(sa1.z); sa1.w = tf32_round(sa1.w);
            sb0.x = tf32_round(sb0.x); sb0.y = tf32_round(sb0.y);
            sb0.z = tf32_round(sb0.z); sb0.w = tf32_round(sb0.w);
            sb1.x = tf32_round(sb1.x); sb1.y = tf32_round(sb1.y);
            sb1.z = tf32_round(sb1.z); sb1.w = tf32_round(sb1.w);
        }
        *(float4*)&As[bf][ar][ac]      = sa0;
        *(float4*)&As[bf][ar + 64][ac] = sa1;
        if (TRB) {
            Bs[bf][bg4 + 0][bk_] = sb0.x;
            Bs[bf][bg4 + 1][bk_] = sb0.y;
            Bs[bf][bg4 + 2][bk_] = sb0.z;
            Bs[bf][bg4 + 3][bk_] = sb0.w;
            Bs[bf][bg4 + 64][bk_] = sb1.x;
            Bs[bf][bg4 + 65][bk_] = sb1.y;
            Bs[bf][bg4 + 66][bk_] = sb1.z;
            Bs[bf][bg4 + 67][bk_] = sb1.w;
        } else {
            *(float4*)&Bs[bf][ar][ac]      = sb0;
            *(float4*)&Bs[bf][ar + 64][ac] = sb1;
        }
    };

    auto compute = [&](int bf) {
#pragma unroll
        for (int kk = 0; kk < BK; kk += 8) {
            uint32_t ah[4][4], al[4][4], bh[4][2], bl[4][2];
#pragma unroll
            for (int mt = 0; mt < 4; mt++) {
                const float2 t0 = *(const float2*)&As[bf][wm0 + mt * 16 + lr][kk + lc2];
                const float2 t1 = *(const float2*)&As[bf][wm0 + mt * 16 + lr + 8][kk + lc2];
                if (THREE) {
                    ah[mt][0] = f2tf32(t0.x); al[mt][0] = __float_as_uint(t0.x - __uint_as_float(ah[mt][0]));
                    ah[mt][2] = f2tf32(t0.y); al[mt][2] = __float_as_uint(t0.y - __uint_as_float(ah[mt][2]));
                    ah[mt][1] = f2tf32(t1.x); al[mt][1] = __float_as_uint(t1.x - __uint_as_float(ah[mt][1]));
                    ah[mt][3] = f2tf32(t1.y); al[mt][3] = __float_as_uint(t1.y - __uint_as_float(ah[mt][3]));
                } else {
                    ah[mt][0] = __float_as_uint(t0.x); ah[mt][2] = __float_as_uint(t0.y);
                    ah[mt][1] = __float_as_uint(t1.x); ah[mt][3] = __float_as_uint(t1.y);
                }
            }
#pragma unroll
            for (int nt = 0; nt < 4; nt++) {
                const float2 t = *(const float2*)&Bs[bf][wn0 + nt * 8 + lr][kk + lc2];
                if (THREE) {
                    bh[nt][0] = f2tf32(t.x); bl[nt][0] = __float_as_uint(t.x - __uint_as_float(bh[nt][0]));
                    bh[nt][1] = f2tf32(t.y); bl[nt][1] = __float_as_uint(t.y - __uint_as_float(bh[nt][1]));
                } else {
                    bh[nt][0] = __float_as_uint(t.x); bh[nt][1] = __float_as_uint(t.y);
                }
            }
#pragma unroll
            for (int mt = 0; mt < 4; mt++)
#pragma unroll
                for (int nt = 0; nt < 4; nt++) {
                    mma8(acc[mt][nt], ah[mt], bh[nt]);
                    if (THREE) {
                        mma8(acc[mt][nt], al[mt], bh[nt]);
                        mma8(acc[mt][nt], ah[mt], bl[nt]);
                    }
                }
        }
    };

    store_tiles(0, a0, a1, b0, b1);
    __syncthreads();

    const int KT = K / BK;
    int buf = 0;
    for (int t = 1; t <= KT; t++) {
        if (t < KT) {
            const int ko = t * BK;
            a0 = *(const float4*)(Ap0 + ko);
            a1 = *(const float4*)(Ap1 + ko);
            if (TRB) {
                b0 = *(const float4*)(Bp0 + (size_t)ko * ldb);
                b1 = *(const float4*)(Bp1 + (size_t)ko * ldb);
            } else {
                b0 = *(const float4*)(Bp0 + ko);
                b1 = *(const float4*)(Bp1 + ko);
            }
        }
        compute(buf);
        if (t < KT) {
            buf ^= 1;
            store_tiles(buf, a0, a1, b0, b1);
            __syncthreads();
        }
    }

    // epilogue
#pragma unroll
    for (int mt = 0; mt < 4; mt++) {
#pragma unroll
        for (int h = 0; h < 2; h++) {
            const size_t r = row0 + wm0 + mt * 16 + lr + h * 8;
            float* Crow = C + r * (size_t)ldc + col0;
#pragma unroll
            for (int nt = 0; nt < 4; nt++) {
                const int cc = wn0 + nt * 8 + lc2;
                float2 v;
                v.x = acc[mt][nt][h * 2 + 0];
                v.y = acc[mt][nt][h * 2 + 1];
                if (Res) {
                    const float2 rv = *(const float2*)(Res + r * (size_t)ldc + col0 + cc);
                    v.x += rv.x; v.y += rv.y;
                }
                if (RND) { v.x = tf32_round(v.x); v.y = tf32_round(v.y); }
                *(float2*)(Crow + cc) = v;
            }
        }
    }
    (void)q;
}

// ---------------- row softmax over 8192-wide rows, in place ------------------
__device__ __forceinline__ float warp_max(float v) {
#pragma unroll
    for (int o = 16; o > 0; o >>= 1) v = fmaxf(v, __shfl_xor_sync(0xffffffffu, v, o));
    return v;
}
__device__ __forceinline__ float warp_sum(float v) {
#pragma unroll
    for (int o = 16; o > 0; o >>= 1) v += __shfl_xor_sync(0xffffffffu, v, o);
    return v;
}

__global__ __launch_bounds__(256)
void softmax_kernel(float* __restrict__ S)
{
    __shared__ float row[NTOK];
    __shared__ float red[8];
    const int tid = threadIdx.x;
    float* Sr = S + (size_t)blockIdx.x * NTOK;

    float lmax = -3.4e38f;
    for (int i = tid; i < NTOK / 4; i += 256) {
        const float4 v = ((const float4*)Sr)[i];
        ((float4*)row)[i] = v;
        lmax = fmaxf(lmax, fmaxf(fmaxf(v.x, v.y), fmaxf(v.z, v.w)));
    }
    lmax = warp_max(lmax);
    if ((tid & 31) == 0) red[tid >> 5] = lmax;
    __syncthreads();
    float rmax = red[0];
#pragma unroll
    for (int w = 1; w < 8; w++) rmax = fmaxf(rmax, red[w]);
    __syncthreads();

    float lsum = 0.f;
    for (int i = tid; i < NTOK / 4; i += 256) {
        float4 v = ((const float4*)row)[i];
        v.x = __expf(v.x - rmax);
        v.y = __expf(v.y - rmax);
        v.z = __expf(v.z - rmax);
        v.w = __expf(v.w - rmax);
        lsum += v.x + v.y + v.z + v.w;
        ((float4*)row)[i] = v;
    }
    lsum = warp_sum(lsum);
    if ((tid & 31) == 0) red[tid >> 5] = lsum;
    __syncthreads();
    float rsum = 0.f;
#pragma unroll
    for (int w = 0; w < 8; w++) rsum += red[w];
    const float inv = 1.f / rsum;

    // normalize + round to tf32 so the PV mma sees exact operands (no trunc bias)
    for (int i = tid; i < NTOK / 4; i += 256) {
        float4 v = ((const float4*)row)[i];
        v.x = tf32_round(v.x * inv);
        v.y = tf32_round(v.y * inv);
        v.z = tf32_round(v.z * inv);
        v.w = tf32_round(v.w * inv);
        ((float4*)Sr)[i] = v;
    }
}

// ---------------- launch -----------------------------------------------------
extern "C" void kernel_launch(void* const* d_in, const int* in_sizes, int n_in,
                              void* d_out, int out_size)
{
    const float* im1 = (const float*)d_in[0];
    const float* im2 = (const float*)d_in[1];
    const float* Wq  = (const float*)d_in[2];
    const float* Wk  = (const float*)d_in[3];
    const float* Wv  = (const float*)d_in[4];

    float* out1 = (float*)d_out;
    float* out2 = out1 + (size_t)NTOK * CDIM;

    float *pS, *pQK1, *pQK2, *pV1, *pV2, *pWqk;
    cudaGetSymbolAddress((void**)&pS,   g_S);
    cudaGetSymbolAddress((void**)&pQK1, g_QK1);
    cudaGetSymbolAddress((void**)&pQK2, g_QK2);
    cudaGetSymbolAddress((void**)&pV1,  g_V1);
    cudaGetSymbolAddress((void**)&pV2,  g_V2);
    cudaGetSymbolAddress((void**)&pWqk, g_Wqk);

    const dim3 blk(256);

    pack_wqk<<<(CDIM * 128) / 256, blk>>>(Wq, Wk, pWqk);

    // Q/K projections: 3xTF32 (near-fp32 logit precision), keep fp32 outputs
    gemm_tf32<true, false, true><<<dim3(1, 64), blk>>>(im1, CDIM, pWqk, 128, nullptr, pQK1, 128, CDIM);
    gemm_tf32<true, false, true><<<dim3(1, 64), blk>>>(im2, CDIM, pWqk, 128, nullptr, pQK2, 128, CDIM);
    // V projections: single-pass tf32 (rna-staged), outputs rounded to tf32
    gemm_tf32<false, true, true><<<dim3(4, 64), blk>>>(im1, CDIM, Wv, CDIM, nullptr, pV1, CDIM, CDIM);
    gemm_tf32<false, true, true><<<dim3(4, 64), blk>>>(im2, CDIM, Wv, CDIM, nullptr, pV2, CDIM, CDIM);

    // stream 1: out1 = softmax(Q2 @ K1^T) @ V1 + im1
    gemm_tf32<true, false, false><<<dim3(64, 64), blk>>>(pQK2, 128, pQK1 + 64, 128, nullptr, pS, NTOK, 64);
    softmax_kernel<<<NTOK, blk>>>(pS);
    gemm_tf32<false, false, true><<<dim3(4, 64), blk>>>(pS, NTOK, pV1, CDIM, im1, out1, CDIM, NTOK);

    // stream 2: out2 = softmax(Q1 @ K2^T) @ V2 + im2
    gemm_tf32<true, false, false><<<dim3(64, 64), blk>>>(pQK1, 128, pQK2 + 64, 128, nullptr, pS, NTOK, 64);
    softmax_kernel<<<NTOK, blk>>>(pS);
    gemm_tf32<false, false, true><<<dim3(4, 64), blk>>>(pS, NTOK, pV2, CDIM, im2, out2, CDIM, NTOK);
}

// round 4
// speedup vs baseline: 4.1482x; 1.1453x over previous
#include <cuda_runtime.h>
#include <cstdint>
#include <cstddef>

#define NTOK 8192
#define CDIM 512

// ---------------- scratch (device globals; no allocations allowed) ----------
__device__ float g_S1[(size_t)NTOK * NTOK];
__device__ float g_S2[(size_t)NTOK * NTOK];
__device__ float g_QK1[(size_t)NTOK * 128];
__device__ float g_QK2[(size_t)NTOK * 128];
__device__ float g_V1[(size_t)NTOK * CDIM];
__device__ float g_V2[(size_t)NTOK * CDIM];
__device__ float g_Wqk[(size_t)CDIM * 128];
__device__ float g_rmax[2 * NTOK];
__device__ float g_rinv[2 * NTOK];

// ---------------- helpers ----------------------------------------------------
__device__ __forceinline__ uint32_t f2tf32(float x) {
    uint32_t r;
    asm("cvt.rna.tf32.f32 %0, %1;" : "=r"(r) : "f"(x));
    return r;
}
__device__ __forceinline__ float tf32_round(float x) { return __uint_as_float(f2tf32(x)); }

__device__ __forceinline__ void mma8(float* c, const uint32_t* a, const uint32_t* b) {
    asm volatile(
        "mma.sync.aligned.m16n8k8.row.col.f32.tf32.tf32.f32 "
        "{%0,%1,%2,%3}, {%4,%5,%6,%7}, {%8,%9}, {%0,%1,%2,%3};"
        : "+f"(c[0]), "+f"(c[1]), "+f"(c[2]), "+f"(c[3])
        : "r"(a[0]), "r"(a[1]), "r"(a[2]), "r"(a[3]), "r"(b[0]), "r"(b[1]));
}

__global__ void pack_wqk(const float* __restrict__ Wq, const float* __restrict__ Wk,
                         float* __restrict__ Wqk) {
    const int i = blockIdx.x * 256 + threadIdx.x;   // 512*128
    const int r = i >> 7, c = i & 127;
    Wqk[i] = (c < 64) ? Wq[r * 64 + c] : Wk[r * 64 + (c - 64)];
}

// ================= 3xTF32 error-compensated GEMM (near-fp32) =================
// 256 threads, block 128x128, warp tile 64x32. z batches two problems.
// TRB=true : B row-major [K x N] (transposed into smem)
// TRB=false: B row-major [N x K]
template<bool TRB>
__global__ __launch_bounds__(256, 2)
void gemm3x(const float* __restrict__ A0, const float* __restrict__ A1, int lda,
            const float* __restrict__ B0, const float* __restrict__ B1, int ldb,
            float* __restrict__ C0, float* __restrict__ C1, int ldc, int K)
{
    constexpr int BK = 16, STR = BK + 8;
    __shared__ float As[2][128][STR];
    __shared__ float Bs[2][128][STR];

    const float* A = blockIdx.z ? A1 : A0;
    const float* B = blockIdx.z ? B1 : B0;
    float*       C = blockIdx.z ? C1 : C0;

    const int tid  = threadIdx.x;
    const int lane = tid & 31;
    const int wid  = tid >> 5;
    const int wm0  = (wid & 1) << 6;
    const int wn0  = (wid >> 1) << 5;
    const int lr   = lane >> 2;
    const int lc2  = (lane & 3) << 1;

    const size_t row0 = (size_t)blockIdx.y * 128;
    const size_t col0 = (size_t)blockIdx.x * 128;

    const int ar = tid >> 2;
    const int ac = (tid & 3) << 2;
    const float* Ap0 = A + (row0 + ar) * (size_t)lda + ac;
    const float* Ap1 = Ap0 + (size_t)64 * lda;

    const float *Bp0, *Bp1;
    int bk_ = 0, bg4 = 0;
    if (TRB) {
        bk_ = tid & 15;
        bg4 = (tid >> 4) << 2;
        Bp0 = B + (size_t)bk_ * ldb + col0 + bg4;
        Bp1 = Bp0 + 64;
    } else {
        Bp0 = B + (col0 + ar) * (size_t)ldb + ac;
        Bp1 = Bp0 + (size_t)64 * ldb;
    }

    float4 a0 = *(const float4*)Ap0;
    float4 a1 = *(const float4*)Ap1;
    float4 b0 = *(const float4*)Bp0;
    float4 b1 = *(const float4*)Bp1;

    float acc[4][4][4];
#pragma unroll
    for (int i = 0; i < 4; i++)
#pragma unroll
        for (int j = 0; j < 4; j++)
#pragma unroll
            for (int k = 0; k < 4; k++) acc[i][j][k] = 0.f;

    auto store_tiles = [&](int bf, float4 sa0, float4 sa1, float4 sb0, float4 sb1) {
        *(float4*)&As[bf][ar][ac]      = sa0;
        *(float4*)&As[bf][ar + 64][ac] = sa1;
        if (TRB) {
            Bs[bf][bg4 + 0][bk_] = sb0.x;
            Bs[bf][bg4 + 1][bk_] = sb0.y;
            Bs[bf][bg4 + 2][bk_] = sb0.z;
            Bs[bf][bg4 + 3][bk_] = sb0.w;
            Bs[bf][bg4 + 64][bk_] = sb1.x;
            Bs[bf][bg4 + 65][bk_] = sb1.y;
            Bs[bf][bg4 + 66][bk_] = sb1.z;
            Bs[bf][bg4 + 67][bk_] = sb1.w;
        } else {
            *(float4*)&Bs[bf][ar][ac]      = sb0;
            *(float4*)&Bs[bf][ar + 64][ac] = sb1;
        }
    };

    auto compute = [&](int bf) {
#pragma unroll
        for (int kk = 0; kk < BK; kk += 8) {
            uint32_t ah[4][4], al[4][4], bh[4][2], bl[4][2];
#pragma unroll
            for (int mt = 0; mt < 4; mt++) {
                const float2 t0 = *(const float2*)&As[bf][wm0 + mt * 16 + lr][kk + lc2];
                const float2 t1 = *(const float2*)&As[bf][wm0 + mt * 16 + lr + 8][kk + lc2];
                ah[mt][0] = f2tf32(t0.x); al[mt][0] = __float_as_uint(t0.x - __uint_as_float(ah[mt][0]));
                ah[mt][2] = f2tf32(t0.y); al[mt][2] = __float_as_uint(t0.y - __uint_as_float(ah[mt][2]));
                ah[mt][1] = f2tf32(t1.x); al[mt][1] = __float_as_uint(t1.x - __uint_as_float(ah[mt][1]));
                ah[mt][3] = f2tf32(t1.y); al[mt][3] = __float_as_uint(t1.y - __uint_as_float(ah[mt][3]));
            }
#pragma unroll
            for (int nt = 0; nt < 4; nt++) {
                const float2 t = *(const float2*)&Bs[bf][wn0 + nt * 8 + lr][kk + lc2];
                bh[nt][0] = f2tf32(t.x); bl[nt][0] = __float_as_uint(t.x - __uint_as_float(bh[nt][0]));
                bh[nt][1] = f2tf32(t.y); bl[nt][1] = __float_as_uint(t.y - __uint_as_float(bh[nt][1]));
            }
#pragma unroll
            for (int mt = 0; mt < 4; mt++)
#pragma unroll
                for (int nt = 0; nt < 4; nt++) {
                    mma8(acc[mt][nt], ah[mt], bh[nt]);
                    mma8(acc[mt][nt], al[mt], bh[nt]);
                    mma8(acc[mt][nt], ah[mt], bl[nt]);
                }
        }
    };

    store_tiles(0, a0, a1, b0, b1);
    __syncthreads();

    const int KT = K / BK;
    int buf = 0;
    for (int t = 1; t <= KT; t++) {
        if (t < KT) {
            const int ko = t * BK;
            a0 = *(const float4*)(Ap0 + ko);
            a1 = *(const float4*)(Ap1 + ko);
            if (TRB) {
                b0 = *(const float4*)(Bp0 + (size_t)ko * ldb);
                b1 = *(const float4*)(Bp1 + (size_t)ko * ldb);
            } else {
                b0 = *(const float4*)(Bp0 + ko);
                b1 = *(const float4*)(Bp1 + ko);
            }
        }
        compute(buf);
        if (t < KT) {
            buf ^= 1;
            store_tiles(buf, a0, a1, b0, b1);
            __syncthreads();
        }
    }

#pragma unroll
    for (int mt = 0; mt < 4; mt++) {
#pragma unroll
        for (int h = 0; h < 2; h++) {
            const size_t r = row0 + wm0 + mt * 16 + lr + h * 8;
            float* Crow = C + r * (size_t)ldc + col0;
#pragma unroll
            for (int nt = 0; nt < 4; nt++) {
                const int cc = wn0 + nt * 8 + lc2;
                float2 v;
                v.x = acc[mt][nt][h * 2 + 0];
                v.y = acc[mt][nt][h * 2 + 1];
                *(float2*)(Crow + cc) = v;
            }
        }
    }
}

// ================= fast single-pass TF32 GEMM ================================
// 128 threads, block 128x128, warp tile 64x64 (0.5 LDS.64 per MMA).
// B is row-major [K x N], transposed into smem. z batches two problems.
// EXPA: stage A as tf32(exp(a - rowmax)*rowinv)  (PV: A = raw logits S)
//       EXPA also enables the residual add (Res + C).
// RNDOUT: round outputs to tf32 (V projection, so PV sees exact operands).
// Staged operands are always tf32-rna rounded -> single-pass mma is exact.
template<bool EXPA, bool RNDOUT>
__global__ __launch_bounds__(128, 2)
void gemm_fast(const float* __restrict__ A0, const float* __restrict__ A1, int lda,
               const float* __restrict__ B0, const float* __restrict__ B1, int ldb,
               const float* __restrict__ R0, const float* __restrict__ R1,
               float* __restrict__ C0, float* __restrict__ C1, int ldc, int K,
               const float* __restrict__ SM, const float* __restrict__ SI)
{
    constexpr int STR = 24;
    __shared__ float As[2][128][STR];
    __shared__ float Bs[2][128][STR];

    const int z = blockIdx.z;
    const float* A   = z ? A1 : A0;
    const float* B   = z ? B1 : B0;
    const float* Res = z ? R1 : R0;
    float*       C   = z ? C1 : C0;

    const int tid  = threadIdx.x;
    const int lane = tid & 31;
    const int wid  = tid >> 5;              // 0..3
    const int wm0  = (wid & 1) << 6;        // 0,64
    const int wn0  = (wid >> 1) << 6;       // 0,64
    const int lr   = lane >> 2;
    const int lc2  = (lane & 3) << 1;

    const size_t row0 = (size_t)blockIdx.y * 128;
    const size_t col0 = (size_t)blockIdx.x * 128;

    // A loader: 4 rows (arr+32j), one float4 each
    const int arr = tid >> 2;               // 0..31
    const int ac4 = (tid & 3) << 2;
    const float* Apb = A + (row0 + arr) * (size_t)lda + ac4;
    const size_t astr = (size_t)32 * lda;

    float rm[4], ri[4];
    if (EXPA) {
#pragma unroll
        for (int j = 0; j < 4; j++) {
            const size_t r = row0 + arr + 32 * j;
            rm[j] = SM[(size_t)z * NTOK + r];
            ri[j] = SI[(size_t)z * NTOK + r];
        }
    }

    // B loader (transpose): k = tid&15, 16-col group per (tid>>4)
    const int bk  = tid & 15;
    const int bn0 = (tid >> 4) << 4;        // 0,16,...,112
    const float* Bpb = B + (size_t)bk * ldb + col0 + bn0;

    float acc[4][8][4];
#pragma unroll
    for (int i = 0; i < 4; i++)
#pragma unroll
        for (int j = 0; j < 8; j++)
#pragma unroll
            for (int k = 0; k < 4; k++) acc[i][j][k] = 0.f;

    auto stage = [&](int bf, const float4* av, const float4* bv) {
#pragma unroll
        for (int j = 0; j < 4; j++) {
            float4 v = av[j];
            if (EXPA) {
                v.x = __expf(v.x - rm[j]) * ri[j];
                v.y = __expf(v.y - rm[j]) * ri[j];
                v.z = __expf(v.z - rm[j]) * ri[j];
                v.w = __expf(v.w - rm[j]) * ri[j];
            }
            v.x = tf32_round(v.x); v.y = tf32_round(v.y);
            v.z = tf32_round(v.z); v.w = tf32_round(v.w);
            *(float4*)&As[bf][arr + 32 * j][ac4] = v;
        }
#pragma unroll
        for (int i = 0; i < 4; i++) {
            float4 v = bv[i];
            v.x = tf32_round(v.x); v.y = tf32_round(v.y);
            v.z = tf32_round(v.z); v.w = tf32_round(v.w);
            const int nb = bn0 + 4 * i;
            Bs[bf][nb + 0][bk] = v.x;
            Bs[bf][nb + 1][bk] = v.y;
            Bs[bf][nb + 2][bk] = v.z;
            Bs[bf][nb + 3][bk] = v.w;
        }
    };

    float4 av[4], bv[4];
#pragma unroll
    for (int j = 0; j < 4; j++) av[j] = *(const float4*)(Apb + j * astr);
#pragma unroll
    for (int i = 0; i < 4; i++) bv[i] = *(const float4*)(Bpb + 4 * i);
    stage(0, av, bv);
    __syncthreads();

    const int KT = K / 16;
    int buf = 0;
    for (int t = 1; t <= KT; t++) {
        if (t < KT) {
            const size_t ko = (size_t)t * 16;
#pragma unroll
            for (int j = 0; j < 4; j++) av[j] = *(const float4*)(Apb + j * astr + ko);
#pragma unroll
            for (int i = 0; i < 4; i++) bv[i] = *(const float4*)(Bpb + ko * ldb + 4 * i);
        }
#pragma unroll
        for (int kk = 0; kk < 16; kk += 8) {
            uint32_t ah[4][4], bh[8][2];
#pragma unroll
            for (int mt = 0; mt < 4; mt++) {
                const float2 t0 = *(const float2*)&As[buf][wm0 + mt * 16 + lr][kk + lc2];
                const float2 t1 = *(const float2*)&As[buf][wm0 + mt * 16 + lr + 8][kk + lc2];
                ah[mt][0] = __float_as_uint(t0.x);
                ah[mt][1] = __float_as_uint(t1.x);
                ah[mt][2] = __float_as_uint(t0.y);
                ah[mt][3] = __float_as_uint(t1.y);
            }
#pragma unroll
            for (int nt = 0; nt < 8; nt++) {
                const float2 t = *(const float2*)&Bs[buf][wn0 + nt * 8 + lr][kk + lc2];
                bh[nt][0] = __float_as_uint(t.x);
                bh[nt][1] = __float_as_uint(t.y);
            }
#pragma unroll
            for (int mt = 0; mt < 4; mt++)
#pragma unroll
                for (int nt = 0; nt < 8; nt++)
                    mma8(acc[mt][nt], ah[mt], bh[nt]);
        }
        if (t < KT) {
            buf ^= 1;
            stage(buf, av, bv);
            __syncthreads();
        }
    }

    // epilogue
#pragma unroll
    for (int mt = 0; mt < 4; mt++) {
#pragma unroll
        for (int h = 0; h < 2; h++) {
            const size_t r = row0 + wm0 + mt * 16 + lr + h * 8;
            float* Crow = C + r * (size_t)ldc + col0;
            const float* Rrow = EXPA ? (Res + r * (size_t)ldc + col0) : nullptr;
#pragma unroll
            for (int nt = 0; nt < 8; nt++) {
                const int cc = wn0 + nt * 8 + lc2;
                float2 v;
                v.x = acc[mt][nt][h * 2 + 0];
                v.y = acc[mt][nt][h * 2 + 1];
                if (EXPA) {
                    const float2 rv = *(const float2*)(Rrow + cc);
                    v.x += rv.x; v.y += rv.y;
                }
                if (RNDOUT) { v.x = tf32_round(v.x); v.y = tf32_round(v.y); }
                *(float2*)(Crow + cc) = v;
            }
        }
    }
}

// ---------------- row stats: max and 1/sum(exp(x-max)) per 8192-row ---------
__device__ __forceinline__ float warp_max(float v) {
#pragma unroll
    for (int o = 16; o > 0; o >>= 1) v = fmaxf(v, __shfl_xor_sync(0xffffffffu, v, o));
    return v;
}
__device__ __forceinline__ float warp_sum(float v) {
#pragma unroll
    for (int o = 16; o > 0; o >>= 1) v += __shfl_xor_sync(0xffffffffu, v, o);
    return v;
}

__global__ __launch_bounds__(256)
void rowstats(const float* __restrict__ S1, const float* __restrict__ S2,
              float* __restrict__ rmax, float* __restrict__ rinv)
{
    __shared__ float row[NTOK];
    __shared__ float red[8];
    const int tid = threadIdx.x;
    const float* S = blockIdx.y ? S2 : S1;
    const float* Sr = S + (size_t)blockIdx.x * NTOK;

    float lmax = -3.4e38f;
    for (int i = tid; i < NTOK / 4; i += 256) {
        const float4 v = ((const float4*)Sr)[i];
        ((float4*)row)[i] = v;
        lmax = fmaxf(lmax, fmaxf(fmaxf(v.x, v.y), fmaxf(v.z, v.w)));
    }
    lmax = warp_max(lmax);
    if ((tid & 31) == 0) red[tid >> 5] = lmax;
    __syncthreads();
    float m = red[0];
#pragma unroll
    for (int w = 1; w < 8; w++) m = fmaxf(m, red[w]);
    __syncthreads();

    float lsum = 0.f;
    for (int i = tid; i < NTOK / 4; i += 256) {
        const float4 v = ((const float4*)row)[i];
        lsum += __expf(v.x - m) + __expf(v.y - m) + __expf(v.z - m) + __expf(v.w - m);
    }
    lsum = warp_sum(lsum);
    if ((tid & 31) == 0) red[tid >> 5] = lsum;
    __syncthreads();
    if (tid == 0) {
        float s = 0.f;
#pragma unroll
        for (int w = 0; w < 8; w++) s += red[w];
        const size_t idx = (size_t)blockIdx.y * NTOK + blockIdx.x;
        rmax[idx] = m;
        rinv[idx] = 1.f / s;
    }
}

// ---------------- launch -----------------------------------------------------
extern "C" void kernel_launch(void* const* d_in, const int* in_sizes, int n_in,
                              void* d_out, int out_size)
{
    const float* im1 = (const float*)d_in[0];
    const float* im2 = (const float*)d_in[1];
    const float* Wq  = (const float*)d_in[2];
    const float* Wk  = (const float*)d_in[3];
    const float* Wv  = (const float*)d_in[4];

    float* out1 = (float*)d_out;
    float* out2 = out1 + (size_t)NTOK * CDIM;

    float *pS1, *pS2, *pQK1, *pQK2, *pV1, *pV2, *pWqk, *pRM, *pRI;
    cudaGetSymbolAddress((void**)&pS1,  g_S1);
    cudaGetSymbolAddress((void**)&pS2,  g_S2);
    cudaGetSymbolAddress((void**)&pQK1, g_QK1);
    cudaGetSymbolAddress((void**)&pQK2, g_QK2);
    cudaGetSymbolAddress((void**)&pV1,  g_V1);
    cudaGetSymbolAddress((void**)&pV2,  g_V2);
    cudaGetSymbolAddress((void**)&pWqk, g_Wqk);
    cudaGetSymbolAddress((void**)&pRM,  g_rmax);
    cudaGetSymbolAddress((void**)&pRI,  g_rinv);

    pack_wqk<<<(CDIM * 128) / 256, 256>>>(Wq, Wk, pWqk);

    // Q/K projections (3xTF32, near-fp32): [QKz] = imz @ [Wq|Wk]
    gemm3x<true><<<dim3(1, 64, 2), 256>>>(im1, im2, CDIM, pWqk, pWqk, 128,
                                          pQK1, pQK2, 128, CDIM);
    // V projections (single-pass tf32, rounded outputs)
    gemm_fast<false, true><<<dim3(4, 64, 2), 128>>>(im1, im2, CDIM, Wv, Wv, CDIM,
                                                    nullptr, nullptr, pV1, pV2, CDIM,
                                                    CDIM, nullptr, nullptr);
    // logits (3xTF32): S1 = Q2 @ K1^T, S2 = Q1 @ K2^T
    gemm3x<false><<<dim3(64, 64, 2), 256>>>(pQK2, pQK1, 128, pQK1 + 64, pQK2 + 64, 128,
                                            pS1, pS2, NTOK, 64);
    // per-row softmax stats
    rowstats<<<dim3(NTOK, 2), 256>>>(pS1, pS2, pRM, pRI);
    // PV with fused softmax-normalize in A staging + residual
    gemm_fast<true, false><<<dim3(4, 64, 2), 128>>>(pS1, pS2, NTOK, pV1, pV2, CDIM,
                                                    im1, im2, out1, out2, CDIM,
                                                    NTOK, pRM, pRI);
}